// round 14
// baseline (speedup 1.0000x reference)
#include <cuda_runtime.h>
#include <cuda_bf16.h>
#include <math.h>
#include <stdint.h>

#define CH 256
#define NBATCH 64
#define HW 1024
#define MTOT 65536
#define EPSV 1e-5f
#define T_ITERS 10
#define NCTA 64

// ---------------- device scratch ----------------
__device__ float g_mean[CH];
__device__ float g_msum[CH*NBATCH];
__device__ float g_bias[CH];
__device__ float g_Sig [CH*CH];
__device__ float g_M   [CH*CH];
__device__ float g_part[192*16384];
__device__ __align__(16) __nv_bfloat16 g_xhi[64L*256*1024];
__device__ __align__(16) __nv_bfloat16 g_xlo[64L*256*1024];
__device__ __align__(16) __nv_bfloat16 g_Mhi [CH*CH], g_Mlo [CH*CH];
__device__ __align__(16) __nv_bfloat16 g_Phi [CH*CH], g_Plo [CH*CH];
__device__ __align__(16) __nv_bfloat16 g_T1hi[CH*CH], g_T1lo[CH*CH];
__device__ __align__(16) __nv_bfloat16 g_T2hi[CH*CH], g_T2lo[CH*CH];
__device__ __align__(16) __nv_bfloat16 g_SNhi[CH*CH], g_SNlo[CH*CH];
__device__ __align__(16) __nv_bfloat16 g_Rhi [CH*CH], g_Rlo [CH*CH];
__device__ unsigned g_bar_cnt;

// ---------------- helpers ----------------
__device__ __forceinline__ uint32_t smem_u32(const void* p) {
    uint32_t a;
    asm("{ .reg .u64 t; cvta.to.shared.u64 t, %1; cvt.u32.u64 %0, t; }" : "=r"(a) : "l"(p));
    return a;
}
__device__ __forceinline__ void ldm_x4(uint32_t* r, uint32_t addr) {
    asm volatile("ldmatrix.sync.aligned.m8n8.x4.shared.b16 {%0,%1,%2,%3}, [%4];"
        : "=r"(r[0]), "=r"(r[1]), "=r"(r[2]), "=r"(r[3]) : "r"(addr));
}
__device__ __forceinline__ void ldm_x4t(uint32_t* r, uint32_t addr) {
    asm volatile("ldmatrix.sync.aligned.m8n8.x4.trans.shared.b16 {%0,%1,%2,%3}, [%4];"
        : "=r"(r[0]), "=r"(r[1]), "=r"(r[2]), "=r"(r[3]) : "r"(addr));
}
__device__ __forceinline__ void ldm_x2t(uint32_t* r, uint32_t addr) {
    asm volatile("ldmatrix.sync.aligned.m8n8.x2.trans.shared.b16 {%0,%1}, [%2];"
        : "=r"(r[0]), "=r"(r[1]) : "r"(addr));
}
__device__ __forceinline__ void mma_bf16(float* c, const uint32_t* a, const uint32_t* b) {
    asm volatile("mma.sync.aligned.m16n8k16.row.col.f32.bf16.bf16.f32 "
        "{%0,%1,%2,%3}, {%4,%5,%6,%7}, {%8,%9}, {%0,%1,%2,%3};"
        : "+f"(c[0]), "+f"(c[1]), "+f"(c[2]), "+f"(c[3])
        : "r"(a[0]), "r"(a[1]), "r"(a[2]), "r"(a[3]), "r"(b[0]), "r"(b[1]));
}
__device__ __forceinline__ void cp16(uint32_t dst, const void* src) {
    asm volatile("cp.async.cg.shared.global [%0], [%1], 16;" :: "r"(dst), "l"(src));
}
__device__ __forceinline__ void cp_commit() { asm volatile("cp.async.commit_group;" ::: "memory"); }
template<int N> __device__ __forceinline__ void cp_wait() {
    asm volatile("cp.async.wait_group %0;" :: "n"(N) : "memory");
}
__device__ __forceinline__ void bfsplit(float v, __nv_bfloat16& h, __nv_bfloat16& l) {
    h = __float2bfloat16(v);
    l = __float2bfloat16(v - __bfloat162float(h));
}

// ---------------- monotonic grid barrier: release/acquire ----------------
struct GBar { unsigned nbar = 0; };
__device__ __forceinline__ void gbar(GBar& gb) {
    __syncthreads();
    gb.nbar++;
    if (threadIdx.x == 0) {
        unsigned target = gb.nbar * NCTA;
        asm volatile("red.release.gpu.add.u32 [%0], 1;" :: "l"(&g_bar_cnt) : "memory");
        unsigned v;
        do {
            asm volatile("ld.acquire.gpu.u32 %0, [%1];" : "=r"(v) : "l"(&g_bar_cnt) : "memory");
        } while (v < target);
    }
    __syncthreads();
}

// ---------------- convert X -> bf16 hi/lo + per-(c,n) sums ----------------
__global__ void __launch_bounds__(256) k_conv1(const float* __restrict__ X) {
    int c = blockIdx.x, n = blockIdx.y, t = threadIdx.x;
    if (c == 0 && n == 0 && t == 0) g_bar_cnt = 0;
    size_t base = ((size_t)n*CH + c) * HW;
    float4 v = *(const float4*)(X + base + t*4);
    float f[4] = {v.x, v.y, v.z, v.w};
    __nv_bfloat16 h[4], l[4];
    #pragma unroll
    for (int k = 0; k < 4; k++) bfsplit(f[k], h[k], l[k]);
    __nv_bfloat162* ph = (__nv_bfloat162*)(g_xhi + base);
    __nv_bfloat162* pl = (__nv_bfloat162*)(g_xlo + base);
    ph[t*2]   = __nv_bfloat162(h[0], h[1]);
    ph[t*2+1] = __nv_bfloat162(h[2], h[3]);
    pl[t*2]   = __nv_bfloat162(l[0], l[1]);
    pl[t*2+1] = __nv_bfloat162(l[2], l[3]);
    float s = (f[0] + f[1]) + (f[2] + f[3]);
    #pragma unroll
    for (int o = 16; o > 0; o >>= 1) s += __shfl_xor_sync(~0u, s, o);
    __shared__ float ws[8];
    if ((t & 31) == 0) ws[t >> 5] = s;
    __syncthreads();
    if (t == 0) {
        float tot = 0.f;
        #pragma unroll
        for (int i = 0; i < 8; i++) tot += ws[i];
        g_msum[c*NBATCH + n] = tot;
    }
}

// ---------------- Gram: quadrants x 64 n-splits, 3-stage cp.async, 512 threads ----------------
#define GT 18432u
#define GSTAGE (4u*GT)
#define GRAM_SMEM (3*GSTAGE)
__global__ void __launch_bounds__(512, 1) k_gram_mma() {
    extern __shared__ char sm[];
    int q = blockIdx.x, n = blockIdx.y;
    int ci0 = (q == 2) ? 128 : 0;
    int cj0 = (q == 0) ? 0 : 128;
    bool diag = (q != 1);
    int tid = threadIdx.x, lane = tid & 31, wid = tid >> 5;
    int wm = wid >> 2, wn = wid & 3;
    uint32_t sbase = smem_u32(sm);

    int rowL = tid >> 2, qL = tid & 3;
    const __nv_bfloat16* gAh = g_xhi + ((size_t)n*CH + ci0 + rowL)*HW + qL*16;
    const __nv_bfloat16* gAl = g_xlo + ((size_t)n*CH + ci0 + rowL)*HW + qL*16;
    const __nv_bfloat16* gBh = g_xhi + ((size_t)n*CH + cj0 + rowL)*HW + qL*16;
    const __nv_bfloat16* gBl = g_xlo + ((size_t)n*CH + cj0 + rowL)*HW + qL*16;

    float acc[2][4][4];
    #pragma unroll
    for (int a = 0; a < 2; a++)
        #pragma unroll
        for (int b = 0; b < 4; b++)
            #pragma unroll
            for (int k = 0; k < 4; k++) acc[a][b][k] = 0.f;

    auto prefetch = [&](int kb, int st) {
        uint32_t sb = sbase + st*GSTAGE;
        int pb = kb*64;
        uint32_t dA = sb + rowL*144 + qL*32;
        cp16(dA,           gAh + pb);
        cp16(dA + 16,      gAh + pb + 8);
        cp16(dA + GT,      gAl + pb);
        cp16(dA + GT + 16, gAl + pb + 8);
        if (!diag) {
            uint32_t dB = dA + 2*GT;
            cp16(dB,           gBh + pb);
            cp16(dB + 16,      gBh + pb + 8);
            cp16(dB + GT,      gBl + pb);
            cp16(dB + GT + 16, gBl + pb + 8);
        }
    };

    prefetch(0, 0); cp_commit();
    prefetch(1, 1); cp_commit();
    for (int kb = 0; kb < 16; kb++) {
        int cur = kb % 3;
        if (kb < 15) cp_wait<1>(); else cp_wait<0>();
        __syncthreads();
        if (kb + 2 < 16) { prefetch(kb+2, (kb+2) % 3); cp_commit(); }
        uint32_t sb = sbase + cur*GSTAGE;
        uint32_t bb = sb + (diag ? 0 : 2*GT);
        #pragma unroll
        for (int ks = 0; ks < 4; ks++) {
            int k0 = ks*16;
            uint32_t ah[2][4], al[2][4], bh[4][2], bl[4][2];
            int ar = lane & 15, ac = (lane >> 4) * 8;
            #pragma unroll
            for (int mt = 0; mt < 2; mt++) {
                uint32_t ao = sb + (wm*32 + mt*16 + ar)*144 + (k0 + ac)*2;
                ldm_x4(ah[mt], ao);
                ldm_x4(al[mt], ao + GT);
            }
            // B via non-trans x4: two n8 fragments per call
            int n_off = ((lane >> 4) << 3) + (lane & 7);
            int k_off = k0 + (((lane >> 3) & 1) << 3);
            #pragma unroll
            for (int ntp = 0; ntp < 2; ntp++) {
                uint32_t bo = bb + (wn*32 + ntp*16 + n_off)*144 + k_off*2;
                uint32_t t4[4];
                ldm_x4(t4, bo);
                bh[2*ntp][0]=t4[0]; bh[2*ntp][1]=t4[1];
                bh[2*ntp+1][0]=t4[2]; bh[2*ntp+1][1]=t4[3];
                ldm_x4(t4, bo + GT);
                bl[2*ntp][0]=t4[0]; bl[2*ntp][1]=t4[1];
                bl[2*ntp+1][0]=t4[2]; bl[2*ntp+1][1]=t4[3];
            }
            #pragma unroll
            for (int mt = 0; mt < 2; mt++)
                #pragma unroll
                for (int nt = 0; nt < 4; nt++) {
                    mma_bf16(acc[mt][nt], ah[mt], bh[nt]);
                    mma_bf16(acc[mt][nt], ah[mt], bl[nt]);
                    mma_bf16(acc[mt][nt], al[mt], bh[nt]);
                }
        }
    }
    float* pout = g_part + ((size_t)q*64 + n)*16384;
    int rg = lane >> 2, cg = (lane & 3)*2;
    #pragma unroll
    for (int mt = 0; mt < 2; mt++)
        #pragma unroll
        for (int nt = 0; nt < 4; nt++) {
            int r0 = wm*32 + mt*16 + rg, c0 = wn*32 + nt*8 + cg;
            *(float2*)(pout + r0*128 + c0)     = make_float2(acc[mt][nt][0], acc[mt][nt][1]);
            *(float2*)(pout + (r0+8)*128 + c0) = make_float2(acc[mt][nt][2], acc[mt][nt][3]);
        }
}

// ---------------- solver tile matmul: 512 threads, K-split-2 across warp groups ----------------
template<int TM>
__device__ __forceinline__ void nt_mm2(
    const __nv_bfloat16* __restrict__ Ah, const __nv_bfloat16* __restrict__ Al,
    const __nv_bfloat16* __restrict__ Bh, const __nv_bfloat16* __restrict__ Bl,
    __nv_bfloat16* __restrict__ Chi, __nv_bfloat16* __restrict__ Clo,
    int tr, int tc, int mode, float snorm, char* ns)
{
    constexpr int SA  = TM*72;
    constexpr int SB  = 64*40;
    constexpr int STB = (2*SA + 2*SB)*2;
    constexpr int NT  = (TM == 64) ? 2 : 1;
    constexpr int WNW = (TM == 64) ? 16 : 8;
    int tid = threadIdx.x, lane = tid & 31, wid = tid >> 5;
    int kgrp = wid >> 3;                  // 0: K 0-127, 1: K 128-255
    int wl = wid & 7;
    int wm = (TM == 64) ? (wl >> 1) : (wl >> 2);
    int wn = (TM == 64) ? (wl & 1)  : (wl & 3);
    uint32_t base = smem_u32(ns);

    float acc[NT][4];
    #pragma unroll
    for (int nt = 0; nt < NT; nt++)
        #pragma unroll
        for (int k = 0; k < 4; k++) acc[nt][k] = 0.f;

    int st_tid = tid & 255, st_grp = tid >> 8;
    int brow = st_tid >> 2, bcol = st_tid & 3;

    auto stage = [&](int i) {
        int kb = st_grp*128 + i*64;
        uint32_t sb = base + (st_grp*2 + i)*STB;
        #pragma unroll
        for (int c = 0; c < TM*8; c += 256) {
            int cc = c + st_tid;
            int row = cc >> 3, col = cc & 7;
            uint32_t d = sb + row*144 + col*16;
            cp16(d,        Ah + (tr + row)*256 + kb + col*8);
            cp16(d + SA*2, Al + (tr + row)*256 + kb + col*8);
        }
        uint32_t dB = sb + 2*(SA*2) + brow*80 + bcol*16;
        cp16(dB,        Bh + (kb + brow)*256 + tc + bcol*8);
        cp16(dB + SB*2, Bl + (kb + brow)*256 + tc + bcol*8);
    };

    stage(0); cp_commit();
    stage(1); cp_commit();
    #pragma unroll
    for (int i = 0; i < 2; i++) {
        if (i == 0) cp_wait<1>(); else cp_wait<0>();
        __syncthreads();
        uint32_t sb  = base + (kgrp*2 + i)*STB;
        uint32_t sbB = sb + 2*(SA*2);
        #pragma unroll
        for (int ks = 0; ks < 4; ks++) {
            int k0 = ks*16;
            uint32_t ah[4], al[4], bh[NT][2], bl[NT][2];
            uint32_t ao = sb + (wm*16 + (lane & 15))*144 + (k0 + (lane >> 4)*8)*2;
            ldm_x4(ah, ao);
            ldm_x4(al, ao + SA*2);
            if (TM == 64) {
                uint32_t bo = sbB + (k0 + (lane & 15))*80 + (wn*16 + (lane >> 4)*8)*2;
                uint32_t t4[4];
                ldm_x4t(t4, bo);
                bh[0][0]=t4[0]; bh[0][1]=t4[1]; bh[NT-1][0]=t4[2]; bh[NT-1][1]=t4[3];
                ldm_x4t(t4, bo + SB*2);
                bl[0][0]=t4[0]; bl[0][1]=t4[1]; bl[NT-1][0]=t4[2]; bl[NT-1][1]=t4[3];
            } else {
                uint32_t bo = sbB + (k0 + (lane & 15))*80 + (wn*WNW)*2;
                ldm_x2t(bh[0], bo);
                ldm_x2t(bl[0], bo + SB*2);
            }
            #pragma unroll
            for (int nt = 0; nt < NT; nt++) {
                mma_bf16(acc[nt], ah, bh[nt]);
                mma_bf16(acc[nt], ah, bl[nt]);
                mma_bf16(acc[nt], al, bh[nt]);
            }
        }
    }
    // K-split combine: group 1 -> smem -> group 0
    __syncthreads();
    float* scr = (float*)ns;
    if (kgrp == 1) {
        #pragma unroll
        for (int nt = 0; nt < NT; nt++)
            #pragma unroll
            for (int k = 0; k < 4; k++)
                scr[(wl*32 + lane)*8 + nt*4 + k] = acc[nt][k];
    }
    __syncthreads();
    if (kgrp == 0) {
        #pragma unroll
        for (int nt = 0; nt < NT; nt++)
            #pragma unroll
            for (int k = 0; k < 4; k++)
                acc[nt][k] += scr[(wl*32 + lane)*8 + nt*4 + k];
        int rg = lane >> 2, cg = (lane & 3)*2;
        #pragma unroll
        for (int nt = 0; nt < NT; nt++) {
            int col = tc + wn*WNW + nt*8 + cg;
            #pragma unroll
            for (int half = 0; half < 2; half++) {
                int row = tr + wm*16 + rg + half*8;
                float v0 = acc[nt][half*2], v1 = acc[nt][half*2+1];
                int idx = row*256 + col;
                if (mode == 1) {
                    __nv_bfloat162 ph = *(__nv_bfloat162*)(g_Phi + idx);
                    __nv_bfloat162 pl = *(__nv_bfloat162*)(g_Plo + idx);
                    float p0 = __bfloat162float(ph.x) + __bfloat162float(pl.x);
                    float p1 = __bfloat162float(ph.y) + __bfloat162float(pl.y);
                    v0 = 1.5f*p0 - 0.5f*v0;
                    v1 = 1.5f*p1 - 0.5f*v1;
                } else if (mode == 2) {
                    v0 *= snorm; v1 *= snorm;
                    *(float2*)(g_M + idx) = make_float2(v0, v1);
                }
                __nv_bfloat16 h0, l0, h1, l1;
                bfsplit(v0, h0, l0); bfsplit(v1, h1, l1);
                *(__nv_bfloat162*)(Chi + idx) = __nv_bfloat162(h0, h1);
                *(__nv_bfloat162*)(Clo + idx) = __nv_bfloat162(l0, l1);
            }
        }
    }
}

#define SOLVER_SMEM (4*((2*64*72 + 2*64*40)*2))   // 114688 B

// ---------------- persistent solver (512 threads) ----------------
__global__ void __launch_bounds__(512) k_solver(const float* __restrict__ rot) {
    extern __shared__ __align__(16) char dynsm[];
    int cta = blockIdx.x, tid = threadIdx.x, lane = tid & 31, wid = tid >> 5;
    __shared__ float red[256];
    __shared__ float s_scal[2];
    GBar gb;

    // phase 0: mean reduce (CTAs 0-15, one warp per channel)
    {
        int wg = cta*16 + wid;
        if (wg < 256) {
            float s = g_msum[wg*NBATCH + lane] + g_msum[wg*NBATCH + 32 + lane];
            #pragma unroll
            for (int o = 16; o > 0; o >>= 1) s += __shfl_xor_sync(~0u, s, o);
            if (lane == 0) g_mean[wg] = s * (1.f / (float)MTOT);
        }
    }
    gbar(gb);

    // phase 1: sigfin — 2 threads per (a, b..b+3), t-loop split
    {
        int pair = cta*256 + (tid >> 1);
        int a = pair >> 6, b = (pair & 63) * 4;
        int half = tid & 1;
        int t0 = half*32, t1 = t0 + 32;
        float4 s4 = make_float4(0.f, 0.f, 0.f, 0.f);
        if (a < 128 || b >= 128) {
            int q = (a < 128) ? ((b < 128) ? 0 : 1) : 2;
            const float* pp = g_part + (size_t)q*64*16384 + (a & 127)*128 + (b & 127);
            #pragma unroll 4
            for (int t = t0; t < t1; t++) {
                float4 v = __ldcg((const float4*)(pp + (size_t)t*16384));
                s4.x += v.x; s4.y += v.y; s4.z += v.z; s4.w += v.w;
            }
        } else {
            const float* pp = g_part + (size_t)1*64*16384 + b*128 + (a - 128);
            #pragma unroll 4
            for (int t = t0; t < t1; t++) {
                const float* bb = pp + (size_t)t*16384;
                s4.x += __ldcg(bb); s4.y += __ldcg(bb+128); s4.z += __ldcg(bb+256); s4.w += __ldcg(bb+384);
            }
        }
        float4* scr4 = (float4*)dynsm;
        scr4[tid] = s4;
        __syncthreads();
        if (half == 0) {
            float4 o = scr4[tid + 1];
            s4.x += o.x; s4.y += o.y; s4.z += o.z; s4.w += o.w;
            float ma = g_mean[a];
            float4 mb = *(const float4*)(g_mean + b);
            float4 v = make_float4(s4.x*(1.f/(float)MTOT) - ma*mb.x,
                                   s4.y*(1.f/(float)MTOT) - ma*mb.y,
                                   s4.z*(1.f/(float)MTOT) - ma*mb.z,
                                   s4.w*(1.f/(float)MTOT) - ma*mb.w);
            if (a == b)   v.x += EPSV;
            if (a == b+1) v.y += EPSV;
            if (a == b+2) v.z += EPSV;
            if (a == b+3) v.w += EPSV;
            *(float4*)(g_Sig + a*256 + b) = v;
        }
    }
    gbar(gb);

    // phase 2: trace + init SigN hi/lo, P = I hi/lo, rot hi/lo (float2/thread)
    {
        if (tid < 256) red[tid] = __ldcg(g_Sig + tid*257);
        __syncthreads();
        for (int o = 128; o > 0; o >>= 1) { if (tid < o) red[tid] += red[tid+o]; __syncthreads(); }
        if (tid == 0) { float tr = red[0]; s_scal[0] = 1.f/tr; s_scal[1] = sqrtf(1.f/tr); }
        __syncthreads();
        float sc = s_scal[0];
        int base = cta*1024 + tid*2;
        float2 sg = __ldcg((const float2*)(g_Sig + base));
        float2 rr = __ldcg((const float2*)(rot + base));
        int r = base >> 8, c = base & 255;
        __nv_bfloat16 sh0, sl0, sh1, sl1, rh0, rl0, rh1, rl1;
        bfsplit(sg.x*sc, sh0, sl0); bfsplit(sg.y*sc, sh1, sl1);
        bfsplit(rr.x, rh0, rl0);    bfsplit(rr.y, rh1, rl1);
        __nv_bfloat16 p0 = __float2bfloat16((r == c)   ? 1.f : 0.f);
        __nv_bfloat16 p1 = __float2bfloat16((r == c+1) ? 1.f : 0.f);
        __nv_bfloat16 z  = __float2bfloat16(0.f);
        *(__nv_bfloat162*)(g_SNhi + base) = __nv_bfloat162(sh0, sh1);
        *(__nv_bfloat162*)(g_SNlo + base) = __nv_bfloat162(sl0, sl1);
        *(__nv_bfloat162*)(g_Rhi + base)  = __nv_bfloat162(rh0, rh1);
        *(__nv_bfloat162*)(g_Rlo + base)  = __nv_bfloat162(rl0, rl1);
        *(__nv_bfloat162*)(g_Phi + base)  = __nv_bfloat162(p0, p1);
        *(__nv_bfloat162*)(g_Plo + base)  = __nv_bfloat162(z, z);
    }
    gbar(gb);

    // phase 3: Newton-Schulz on tensor cores
    for (int it = 0; it < T_ITERS; it++) {
        if (cta < 32) {
            int t = cta;
            nt_mm2<64>(g_Phi, g_Plo, g_Phi, g_Plo, g_T1hi, g_T1lo,
                       (t >> 3)*64, (t & 7)*32, 0, 0.f, dynsm);
        } else {
            int t = cta - 32;
            nt_mm2<64>(g_Phi, g_Plo, g_SNhi, g_SNlo, g_T2hi, g_T2lo,
                       (t >> 3)*64, (t & 7)*32, 0, 0.f, dynsm);
        }
        gbar(gb);
        nt_mm2<32>(g_T1hi, g_T1lo, g_T2hi, g_T2lo, g_Phi, g_Plo,
                   (cta >> 3)*32, (cta & 7)*32, 1, 0.f, dynsm);
        gbar(gb);
    }

    // phase 4: M = s * rot * P
    nt_mm2<32>(g_Rhi, g_Rlo, g_Phi, g_Plo, g_Mhi, g_Mlo,
               (cta >> 3)*32, (cta & 7)*32, 2, s_scal[1], dynsm);
    gbar(gb);

    // phase 5: bias (CTAs 0-15)
    {
        int wg = cta*16 + wid;
        if (wg < 256) {
            float s = 0.f;
            #pragma unroll
            for (int k = 0; k < 8; k++)
                s += __ldcg(g_M + wg*256 + lane + k*32) * g_mean[lane + k*32];
            #pragma unroll
            for (int o = 16; o > 0; o >>= 1) s += __shfl_xor_sync(~0u, s, o);
            if (lane == 0) g_bias[wg] = s;
        }
    }
}

// ---------------- persistent output GEMM: M resident in smem, X streamed ----------------
#define OMT 18432u
#define OMREG (8u*OMT)
#define OXT 17408u
#define OXSTAGE (2u*OXT)
#define OUT_SMEM (OMREG + 2*OXSTAGE)
__global__ void __launch_bounds__(512, 1) k_out_mma(float* __restrict__ out) {
    extern __shared__ char sm[];
    int tid = threadIdx.x, lane = tid & 31, wid = tid >> 5;
    int wm = wid >> 2, wn = wid & 3;
    uint32_t sbase = smem_u32(sm);
    int cta = blockIdx.x;
    int d0 = (cta & 1) * 128;
    int combo0 = (cta >> 1) * 8;

    int rowA = tid >> 2, qA = tid & 3;
    #pragma unroll
    for (int c = 0; c < 4; c++) {
        uint32_t dA = sbase + c*(2*OMT) + rowA*144 + qA*32;
        const __nv_bfloat16* mh = g_Mhi + (d0 + rowA)*256 + c*64 + qA*16;
        const __nv_bfloat16* ml = g_Mlo + (d0 + rowA)*256 + c*64 + qA*16;
        cp16(dA,            mh);
        cp16(dA + 16,       mh + 8);
        cp16(dA + OMT,      ml);
        cp16(dA + OMT + 16, ml + 8);
    }
    cp_commit();

    int rowB = tid >> 3, qB = tid & 7;
    auto stageX = [&](int g, int st) {
        int combo = combo0 + (g >> 2);
        int n = combo >> 3, p0 = (combo & 7) * 128;
        int cb = (g & 3) * 64;
        uint32_t dB = sbase + OMREG + st*OXSTAGE + rowB*272 + qB*32;
        const __nv_bfloat16* xh = g_xhi + ((size_t)n*CH + cb + rowB)*HW + p0 + qB*16;
        const __nv_bfloat16* xl = g_xlo + ((size_t)n*CH + cb + rowB)*HW + p0 + qB*16;
        cp16(dB,            xh);
        cp16(dB + 16,       xh + 8);
        cp16(dB + OXT,      xl);
        cp16(dB + OXT + 16, xl + 8);
    };

    stageX(0, 0); cp_commit();

    float acc[2][4][4];
    #pragma unroll
    for (int a = 0; a < 2; a++)
        #pragma unroll
        for (int b = 0; b < 4; b++)
            #pragma unroll
            for (int k = 0; k < 4; k++) acc[a][b][k] = 0.f;

    for (int g = 0; g < 32; g++) {
        int cur = g & 1;
        if (g < 31) { stageX(g+1, cur^1); cp_commit(); cp_wait<1>(); }
        else        { cp_wait<0>(); }
        __syncthreads();
        uint32_t sbM = sbase + (g & 3)*(2*OMT);
        uint32_t sbX = sbase + OMREG + cur*OXSTAGE;
        #pragma unroll
        for (int ks = 0; ks < 4; ks++) {
            int k0 = ks*16;
            uint32_t ah[2][4], al[2][4], bh[4][2], bl[4][2];
            int ar = lane & 15, ac = (lane >> 4) * 8;
            #pragma unroll
            for (int mt = 0; mt < 2; mt++) {
                uint32_t ao = sbM + (wm*32 + mt*16 + ar)*144 + (k0 + ac)*2;
                ldm_x4(ah[mt], ao);
                ldm_x4(al[mt], ao + OMT);
            }
            // B via trans x4: two n8 fragments per call
            #pragma unroll
            for (int ntp = 0; ntp < 2; ntp++) {
                uint32_t bo = sbX + (k0 + (lane & 15))*272 + (wn*32 + ntp*16 + (lane >> 4)*8)*2;
                uint32_t t4[4];
                ldm_x4t(t4, bo);
                bh[2*ntp][0]=t4[0]; bh[2*ntp][1]=t4[1];
                bh[2*ntp+1][0]=t4[2]; bh[2*ntp+1][1]=t4[3];
                ldm_x4t(t4, bo + OXT);
                bl[2*ntp][0]=t4[0]; bl[2*ntp][1]=t4[1];
                bl[2*ntp+1][0]=t4[2]; bl[2*ntp+1][1]=t4[3];
            }
            #pragma unroll
            for (int mt = 0; mt < 2; mt++)
                #pragma unroll
                for (int nt = 0; nt < 4; nt++) {
                    mma_bf16(acc[mt][nt], ah[mt], bh[nt]);
                    mma_bf16(acc[mt][nt], ah[mt], bl[nt]);
                    mma_bf16(acc[mt][nt], al[mt], bh[nt]);
                }
        }
        if ((g & 3) == 3) {
            int combo = combo0 + (g >> 2);
            int n = combo >> 3, p0 = (combo & 7) * 128;
            float* On = out + (size_t)n * (CH*HW);
            int rg = lane >> 2, cg = (lane & 3)*2;
            #pragma unroll
            for (int mt = 0; mt < 2; mt++) {
                int d = d0 + wm*32 + mt*16 + rg;
                float b0 = g_bias[d], b1 = g_bias[d+8];
                #pragma unroll
                for (int nt = 0; nt < 4; nt++) {
                    int p = p0 + wn*32 + nt*8 + cg;
                    *(float2*)(On + (size_t)d*HW + p)     = make_float2(acc[mt][nt][0]-b0, acc[mt][nt][1]-b0);
                    *(float2*)(On + (size_t)(d+8)*HW + p) = make_float2(acc[mt][nt][2]-b1, acc[mt][nt][3]-b1);
                }
            }
            #pragma unroll
            for (int a = 0; a < 2; a++)
                #pragma unroll
                for (int b = 0; b < 4; b++)
                    #pragma unroll
                    for (int k = 0; k < 4; k++) acc[a][b][k] = 0.f;
        }
        __syncthreads();
    }
}

// ---------------- launch ----------------
extern "C" void kernel_launch(void* const* d_in, const int* in_sizes, int n_in,
                              void* d_out, int out_size) {
    const float* X   = (const float*)d_in[0];
    const float* rot = (const float*)d_in[1];
    if (n_in >= 2 && in_sizes[0] == CH*CH && in_sizes[1] != CH*CH) {
        X = (const float*)d_in[1]; rot = (const float*)d_in[0];
    }
    float* out = (float*)d_out;
    (void)out_size;

    cudaFuncSetAttribute(k_gram_mma, cudaFuncAttributeMaxDynamicSharedMemorySize, GRAM_SMEM);
    cudaFuncSetAttribute(k_out_mma,  cudaFuncAttributeMaxDynamicSharedMemorySize, OUT_SMEM);
    cudaFuncSetAttribute(k_solver,   cudaFuncAttributeMaxDynamicSharedMemorySize, SOLVER_SMEM);

    k_conv1<<<dim3(256, 64), 256>>>(X);
    k_gram_mma<<<dim3(3, 64), 512, GRAM_SMEM>>>();
    k_solver<<<NCTA, 512, SOLVER_SMEM>>>(rot);
    k_out_mma<<<128, 512, OUT_SMEM>>>(out);
}